// round 3
// baseline (speedup 1.0000x reference)
#include <cuda_runtime.h>

#define LOG2E 1.4426950408889634f

// ---------------- scratch (device globals; no allocation allowed) ----------
__device__ float g_Q [8192*128];
__device__ float g_K [8192*128];
__device__ float g_V [8192*128];
__device__ float g_O [8192*128];
__device__ float g_Y [8192*128];
__device__ float g_X1[8192*128];
__device__ float g_FF[8192*512];
__device__ float g_red[2][8][2];   // [stage][sample][sum, sumsq]

__device__ __forceinline__ float fexp2(float x){
  float y; asm("ex2.approx.ftz.f32 %0, %1;" : "=f"(y) : "f"(x)); return y;
}

__global__ void zero_red_kernel(){
  int t = threadIdx.x;
  if (t < 32) ((float*)g_red)[t] = 0.f;
}

// ---------------- shared GEMM microkernel: C[64][128], K-chunk=128 ---------
// Thread map: tr = tid>>5 owns rows tr*8..tr*8+7 ; lane owns cols lane*4..+3.
// A-reads broadcast within warp, B-reads coalesced across lanes: conflict-free.
__device__ __forceinline__ void gemm_compute(const float* As, const float* Ws,
                                             float acc[8][4], int r0, int lane){
  #pragma unroll
  for (int k4 = 0; k4 < 32; k4++){
    float4 b0 = ((const float4*)Ws)[(k4*4+0)*32 + lane];
    float4 b1 = ((const float4*)Ws)[(k4*4+1)*32 + lane];
    float4 b2 = ((const float4*)Ws)[(k4*4+2)*32 + lane];
    float4 b3 = ((const float4*)Ws)[(k4*4+3)*32 + lane];
    #pragma unroll
    for (int i = 0; i < 8; i++){
      float4 a = ((const float4*)As)[(r0+i)*32 + k4];
      acc[i][0] += a.x*b0.x + a.y*b1.x + a.z*b2.x + a.w*b3.x;
      acc[i][1] += a.x*b0.y + a.y*b1.y + a.z*b2.y + a.w*b3.y;
      acc[i][2] += a.x*b0.z + a.y*b1.z + a.z*b2.z + a.w*b3.z;
      acc[i][3] += a.x*b0.w + a.y*b1.w + a.z*b2.w + a.w*b3.w;
    }
  }
}

__device__ __forceinline__ void ln_reduce_store(float s, float sq, float* sm,
                                                int tid, int b, int which){
  #pragma unroll
  for (int off = 16; off; off >>= 1){
    s  += __shfl_xor_sync(0xffffffffu, s,  off);
    sq += __shfl_xor_sync(0xffffffffu, sq, off);
  }
  __syncthreads();                 // all compute reads of smem done
  if ((tid & 31) == 0){ sm[tid>>5] = s; sm[8 + (tid>>5)] = sq; }
  __syncthreads();
  if (tid == 0){
    float S = 0.f, SQ = 0.f;
    #pragma unroll
    for (int w = 0; w < 8; w++){ S += sm[w]; SQ += sm[8+w]; }
    atomicAdd(&g_red[which][b][0], S);
    atomicAdd(&g_red[which][b][1], SQ);
  }
}

// ---------------- K1: QKV projections -------------------------------------
// W_query/key/val: [H=4][E=128][K=32]; output column j = h*32+k  -> [8192][128]
__global__ void __launch_bounds__(256) qkv_kernel(const float* __restrict__ x,
    const float* __restrict__ Wq, const float* __restrict__ Wk,
    const float* __restrict__ Wv){
  extern __shared__ float sm[];
  float* As = sm;             // 64*128
  float* Ws = sm + 64*128;    // 128*128
  int row0 = blockIdx.x * 64;
  const float* W = (blockIdx.y==0) ? Wq : (blockIdx.y==1 ? Wk : Wv);
  float* outp    = (blockIdx.y==0) ? g_Q : (blockIdx.y==1 ? g_K : g_V);
  int tid = threadIdx.x;

  #pragma unroll
  for (int rep = 0; rep < 8; rep++){
    int idx = rep*256 + tid;               // 2048 float4
    int r = idx >> 5, k4 = idx & 31;
    ((float4*)As)[idx] = ((const float4*)(x + (size_t)(row0+r)*128))[k4];
  }
  #pragma unroll
  for (int rep = 0; rep < 16; rep++){
    int idx = rep*256 + tid;               // 4096 float4  Ws[e][j]
    int e = idx >> 5, j4 = idx & 31;
    ((float4*)Ws)[idx] =
      *(const float4*)(W + ((j4>>3)<<12) + (e<<5) + ((j4&7)<<2));
  }
  __syncthreads();

  int tr = tid >> 5, lane = tid & 31;
  int r0 = tr*8, c0 = lane*4;
  float acc[8][4];
  #pragma unroll
  for (int i=0;i<8;i++){ acc[i][0]=acc[i][1]=acc[i][2]=acc[i][3]=0.f; }
  gemm_compute(As, Ws, acc, r0, lane);
  #pragma unroll
  for (int i=0;i<8;i++){
    float4 o = make_float4(acc[i][0],acc[i][1],acc[i][2],acc[i][3]);
    *(float4*)(outp + (size_t)(row0+r0+i)*128 + c0) = o;
  }
}

// ---------------- K2: fused attention -------------------------------------
// grid (16, 8) : blockIdx.x = n-tile (64 rows), blockIdx.y = batch
// Per m-tile(64): scores(4 heads) -> 8ch MLP (fused input2 read + passthrough
// write) -> online softmax -> P@V into registers.
__global__ void __launch_bounds__(256,1) attn_kernel(
    const float* __restrict__ in2, float* __restrict__ out2,
    const float* __restrict__ Ws1, const float* __restrict__ bs1,
    const float* __restrict__ Ws2, const float* __restrict__ bs2){
  extern __shared__ float sm[];
  float* Qs      = sm;             // 64*128  XOR-swizzled (16B granule)
  float* Ks      = Qs + 8192;      // 64*128  XOR-swizzled
  float* Vs      = Ks + 8192;      // 64*128  plain
  float* Smat    = Vs + 8192;      // 4*64*65 scores -> logits -> p
  float* alpha_s = Smat + 4*64*65; // 256
  float* rsum_s  = alpha_s + 256;  // 256
  float* mw      = rsum_s + 256;   // 112 MLP weights

  int tid = threadIdx.x;
  int n0  = blockIdx.x * 64;
  int b   = blockIdx.y;

  if (tid < 64)       mw[tid] = Ws1[tid];
  else if (tid < 72)  mw[tid] = bs1[tid-64];
  else if (tid < 104) mw[tid] = Ws2[tid-72];
  else if (tid < 108) mw[tid] = bs2[tid-104];

  // load Q tile (swizzled: k4 ^= (r>>3)&7)
  {
    const float* Qg = g_Q + ((size_t)(b*1024 + n0))*128;
    #pragma unroll
    for (int rep = 0; rep < 8; rep++){
      int idx = rep*256 + tid; int r = idx>>5, k4 = idx&31;
      float4 v = ((const float4*)Qg)[r*32 + k4];
      *(float4*)(Qs + r*128 + ((k4 ^ ((r>>3)&7))<<2)) = v;
    }
  }

  int h = tid >> 6, t = tid & 63;
  int s_ni0 = (t&7)*8, s_mi0 = (t>>3)*8;      // score micro-tile
  int p_ni0 = (t>>3)*8, p_k0  = (t&7)*4;      // PV / output micro-tile
  int qsw = t & 7, ksw = t >> 3;              // per-thread swizzle groups

  float Oa[8][4];
  #pragma unroll
  for (int i=0;i<8;i++){ Oa[i][0]=Oa[i][1]=Oa[i][2]=Oa[i][3]=0.f; }
  float rmax = -1e30f, rsum = 0.f;

  const float* in2b = in2  + (size_t)b*1048576;   // + h*8388608 per head
  float*       o2b  = out2 + (size_t)b*1048576;

  for (int it = 0; it < 16; it++){
    int m0 = it*64;
    __syncthreads();   // prev PV done before K/V/S overwrite
    {
      const float* Kg = g_K + ((size_t)(b*1024 + m0))*128;
      const float* Vg = g_V + ((size_t)(b*1024 + m0))*128;
      #pragma unroll
      for (int rep = 0; rep < 8; rep++){
        int idx = rep*256 + tid; int r = idx>>5, k4 = idx&31;
        float4 kv = ((const float4*)Kg)[r*32 + k4];
        *(float4*)(Ks + r*128 + ((k4 ^ ((r>>3)&7))<<2)) = kv;
        float4 vv = ((const float4*)Vg)[r*32 + k4];
        *(float4*)(Vs + r*128 + (k4<<2)) = vv;
      }
    }
    __syncthreads();

    // ---- scores: S[h][ni][mi] = Q_h . K_h -------------------------------
    {
      float acc2[8][8];
      #pragma unroll
      for (int i=0;i<8;i++)
        #pragma unroll
        for (int j=0;j<8;j++) acc2[i][j] = 0.f;
      int kb = h << 5;
      #pragma unroll
      for (int kk = 0; kk < 32; kk++){
        int k = kb + kk, kidx = k >> 2, kl = k & 3;
        float a[8], bb[8];
        #pragma unroll
        for (int i=0;i<8;i++)
          a[i]  = Qs[(s_ni0+i)*128 + ((kidx ^ qsw)<<2) + kl];
        #pragma unroll
        for (int j=0;j<8;j++)
          bb[j] = Ks[(s_mi0+j)*128 + ((kidx ^ ksw)<<2) + kl];
        #pragma unroll
        for (int i=0;i<8;i++)
          #pragma unroll
          for (int j=0;j<8;j++) acc2[i][j] += a[i]*bb[j];
      }
      #pragma unroll
      for (int i=0;i<8;i++){
        float* Sr = Smat + ((h<<6) + s_ni0 + i)*65 + s_mi0;
        #pragma unroll
        for (int j=0;j<8;j++) Sr[j] = acc2[i][j];
      }
    }
    __syncthreads();

    // ---- 8->8(relu)->4 MLP, fused input2 read + passthrough write -------
    {
      int ni  = tid >> 2;
      int mi0 = (tid & 3) * 4;       // + m4*16
      const float* p0 = in2b + ((size_t)(n0+ni)<<10) + m0;
      float*       q0 = o2b  + ((size_t)(n0+ni)<<10) + m0;
      #pragma unroll
      for (int m4 = 0; m4 < 4; m4++){
        int mbase = mi0 + m4*16;
        float4 t2[4];
        #pragma unroll
        for (int hh=0; hh<4; hh++){
          t2[hh] = *(const float4*)(p0 + (size_t)hh*8388608 + mbase);
          *(float4*)(q0 + (size_t)hh*8388608 + mbase) = t2[hh];
        }
        #pragma unroll
        for (int e=0; e<4; e++){
          int mi = mbase + e;
          float x[8];
          #pragma unroll
          for (int hh=0; hh<4; hh++) x[hh] = Smat[((hh<<6)+ni)*65 + mi];
          x[4] = ((float*)&t2[0])[e]; x[5] = ((float*)&t2[1])[e];
          x[6] = ((float*)&t2[2])[e]; x[7] = ((float*)&t2[3])[e];
          float z[8];
          #pragma unroll
          for (int j=0;j<8;j++) z[j] = mw[64+j];
          #pragma unroll
          for (int i=0;i<8;i++)
            #pragma unroll
            for (int j=0;j<8;j++) z[j] += x[i]*mw[i*8+j];
          #pragma unroll
          for (int j=0;j<8;j++) z[j] = fmaxf(z[j], 0.f);
          float y[4];
          #pragma unroll
          for (int c=0;c<4;c++) y[c] = mw[104+c];
          #pragma unroll
          for (int j=0;j<8;j++)
            #pragma unroll
            for (int c=0;c<4;c++) y[c] += z[j]*mw[72 + j*4 + c];
          #pragma unroll
          for (int hh=0;hh<4;hh++) Smat[((hh<<6)+ni)*65 + mi] = y[hh]*LOG2E;
        }
      }
    }
    __syncthreads();

    // ---- online softmax (1 thread per (h,ni) row) -----------------------
    {
      float* Sr = Smat + tid*65;     // row id == tid (4*64 = 256 rows)
      float mt = -1e30f;
      #pragma unroll 8
      for (int mi=0; mi<64; mi++) mt = fmaxf(mt, Sr[mi]);
      float mnew = fmaxf(rmax, mt);
      float al = fexp2(rmax - mnew);
      float st = 0.f;
      #pragma unroll 8
      for (int mi=0; mi<64; mi++){
        float p = fexp2(Sr[mi] - mnew);
        Sr[mi] = p; st += p;
      }
      rsum = rsum*al + st;
      rmax = mnew;
      alpha_s[tid] = al;
      rsum_s[tid]  = rsum;
    }
    __syncthreads();

    // ---- rescale + P @ V ------------------------------------------------
    {
      #pragma unroll
      for (int i=0;i<8;i++){
        float al = alpha_s[(h<<6) + p_ni0 + i];
        Oa[i][0]*=al; Oa[i][1]*=al; Oa[i][2]*=al; Oa[i][3]*=al;
      }
      #pragma unroll 8
      for (int mi=0; mi<64; mi++){
        float4 v4 = *(float4*)(Vs + mi*128 + (h<<5) + p_k0);
        float p[8];
        #pragma unroll
        for (int i=0;i<8;i++) p[i] = Smat[((h<<6)+p_ni0+i)*65 + mi];
        #pragma unroll
        for (int i=0;i<8;i++){
          Oa[i][0] += p[i]*v4.x; Oa[i][1] += p[i]*v4.y;
          Oa[i][2] += p[i]*v4.z; Oa[i][3] += p[i]*v4.w;
        }
      }
    }
  }

  // final normalize + write heads output
  float* Og = g_O + ((size_t)(b*1024 + n0))*128;
  #pragma unroll
  for (int i=0;i<8;i++){
    float inv = 1.f / rsum_s[(h<<6) + p_ni0 + i];
    float4 o = make_float4(Oa[i][0]*inv, Oa[i][1]*inv, Oa[i][2]*inv, Oa[i][3]*inv);
    *(float4*)(Og + (size_t)(p_ni0+i)*128 + (h<<5) + p_k0) = o;
  }
}

// ---------------- K3: out-projection + residual + LN sums ------------------
// W_out [H][K][E] is already contiguous as [j=h*32+k][e].
__global__ void __launch_bounds__(256) outproj_kernel(
    const float* __restrict__ input1, const float* __restrict__ Wout){
  extern __shared__ float sm[];
  float* As = sm; float* Ws = sm + 64*128;
  int row0 = blockIdx.x * 64; int tid = threadIdx.x;
  #pragma unroll
  for (int rep=0; rep<8; rep++){
    int idx = rep*256 + tid;
    ((float4*)As)[idx] = ((const float4*)(g_O + (size_t)row0*128))[idx];
  }
  #pragma unroll
  for (int rep=0; rep<16; rep++){
    int idx = rep*256 + tid;
    ((float4*)Ws)[idx] = ((const float4*)Wout)[idx];
  }
  __syncthreads();
  int tr = tid>>5, lane = tid&31, r0 = tr*8, c0 = lane*4;
  float acc[8][4];
  #pragma unroll
  for (int i=0;i<8;i++){ acc[i][0]=acc[i][1]=acc[i][2]=acc[i][3]=0.f; }
  gemm_compute(As, Ws, acc, r0, lane);
  float s=0.f, sq=0.f;
  #pragma unroll
  for (int i=0;i<8;i++){
    float4 res = *(const float4*)(input1 + (size_t)(row0+r0+i)*128 + c0);
    float4 o = make_float4(acc[i][0]+res.x, acc[i][1]+res.y,
                           acc[i][2]+res.z, acc[i][3]+res.w);
    *(float4*)(g_Y + (size_t)(row0+r0+i)*128 + c0) = o;
    s  += o.x+o.y+o.z+o.w;
    sq += o.x*o.x+o.y*o.y+o.z*o.z+o.w*o.w;
  }
  ln_reduce_store(s, sq, sm, tid, row0>>10, 0);
}

// ---------------- K5: FF1 (relu) ------------------------------------------
__global__ void __launch_bounds__(256) ff1_kernel(const float* __restrict__ Wff1){
  extern __shared__ float sm[];
  float* As = sm; float* Ws = sm + 64*128;
  int row0 = blockIdx.x * 64, ct = blockIdx.y, tid = threadIdx.x;
  #pragma unroll
  for (int rep=0; rep<8; rep++){
    int idx = rep*256 + tid;
    ((float4*)As)[idx] = ((const float4*)(g_X1 + (size_t)row0*128))[idx];
  }
  #pragma unroll
  for (int rep=0; rep<16; rep++){
    int idx = rep*256 + tid;
    int e = idx>>5, c4 = idx&31;
    ((float4*)Ws)[idx] = *(const float4*)(Wff1 + (size_t)e*512 + ct*128 + c4*4);
  }
  __syncthreads();
  int tr = tid>>5, lane = tid&31, r0 = tr*8, c0 = lane*4;
  float acc[8][4];
  #pragma unroll
  for (int i=0;i<8;i++){ acc[i][0]=acc[i][1]=acc[i][2]=acc[i][3]=0.f; }
  gemm_compute(As, Ws, acc, r0, lane);
  #pragma unroll
  for (int i=0;i<8;i++){
    float4 o = make_float4(fmaxf(acc[i][0],0.f), fmaxf(acc[i][1],0.f),
                           fmaxf(acc[i][2],0.f), fmaxf(acc[i][3],0.f));
    *(float4*)(g_FF + (size_t)(row0+r0+i)*512 + ct*128 + c0) = o;
  }
}

// ---------------- K6: FF2 + residual + LN sums -----------------------------
__global__ void __launch_bounds__(256) ff2_kernel(const float* __restrict__ Wff2){
  extern __shared__ float sm[];
  float* As = sm; float* Ws = sm + 64*128;
  int row0 = blockIdx.x * 64, tid = threadIdx.x;
  int tr = tid>>5, lane = tid&31, r0 = tr*8, c0 = lane*4;
  float acc[8][4];
  #pragma unroll
  for (int i=0;i<8;i++){ acc[i][0]=acc[i][1]=acc[i][2]=acc[i][3]=0.f; }
  for (int ch = 0; ch < 4; ch++){
    __syncthreads();
    #pragma unroll
    for (int rep=0; rep<8; rep++){
      int idx = rep*256 + tid; int r = idx>>5, k4 = idx&31;
      ((float4*)As)[idx] =
        *(const float4*)(g_FF + (size_t)(row0+r)*512 + ch*128 + k4*4);
    }
    #pragma unroll
    for (int rep=0; rep<16; rep++){
      int idx = rep*256 + tid;
      ((float4*)Ws)[idx] = ((const float4*)(Wff2 + (size_t)ch*16384))[idx];
    }
    __syncthreads();
    gemm_compute(As, Ws, acc, r0, lane);
  }
  float s=0.f, sq=0.f;
  #pragma unroll
  for (int i=0;i<8;i++){
    float4 res = *(const float4*)(g_X1 + (size_t)(row0+r0+i)*128 + c0);
    float4 o = make_float4(acc[i][0]+res.x, acc[i][1]+res.y,
                           acc[i][2]+res.z, acc[i][3]+res.w);
    *(float4*)(g_Y + (size_t)(row0+r0+i)*128 + c0) = o;
    s  += o.x+o.y+o.z+o.w;
    sq += o.x*o.x+o.y*o.y+o.z*o.z+o.w*o.w;
  }
  ln_reduce_store(s, sq, sm, tid, row0>>10, 1);
}

// ---------------- K4/K7: global LayerNorm (ddof=1) -------------------------
__global__ void __launch_bounds__(256) norm_kernel(int which, float* extout){
  float* dst = (which == 0) ? g_X1 : extout;
  int id = blockIdx.x*256 + threadIdx.x;          // float4 index, 262144 total
  int b = (id*4) >> 17;                           // 131072 elems per sample
  float s  = g_red[which][b][0];
  float sq = g_red[which][b][1];
  const float M = 131072.f;
  float mean = s / M;
  float var  = (sq - s*s/M) / (M - 1.f);
  float rstd = rsqrtf(var + 1e-5f);
  float4 v = ((const float4*)g_Y)[id];
  v.x = (v.x-mean)*rstd; v.y = (v.y-mean)*rstd;
  v.z = (v.z-mean)*rstd; v.w = (v.w-mean)*rstd;
  ((float4*)dst)[id] = v;
}

// ---------------- launcher --------------------------------------------------
extern "C" void kernel_launch(void* const* d_in, const int* in_sizes, int n_in,
                              void* d_out, int out_size){
  const float* input1 = (const float*)d_in[0];
  const float* input2 = (const float*)d_in[1];
  const float* Wq  = (const float*)d_in[2];
  const float* Wk  = (const float*)d_in[3];
  const float* Wv  = (const float*)d_in[4];
  const float* Wo  = (const float*)d_in[5];
  const float* Ws1 = (const float*)d_in[6];
  const float* bs1 = (const float*)d_in[7];
  const float* Ws2 = (const float*)d_in[8];
  const float* bs2 = (const float*)d_in[9];
  const float* Wff1 = (const float*)d_in[10];
  const float* Wff2 = (const float*)d_in[11];
  float* out1 = (float*)d_out;
  float* out2 = out1 + 8*1024*128;      // input2 passthrough region

  const int GEMM_SMEM = 98304;          // (64*128 + 128*128) * 4
  const int ATTN_SMEM = 167360;         // see layout in attn_kernel

  cudaFuncSetAttribute(qkv_kernel,     cudaFuncAttributeMaxDynamicSharedMemorySize, GEMM_SMEM);
  cudaFuncSetAttribute(attn_kernel,    cudaFuncAttributeMaxDynamicSharedMemorySize, ATTN_SMEM);
  cudaFuncSetAttribute(outproj_kernel, cudaFuncAttributeMaxDynamicSharedMemorySize, GEMM_SMEM);
  cudaFuncSetAttribute(ff1_kernel,     cudaFuncAttributeMaxDynamicSharedMemorySize, GEMM_SMEM);
  cudaFuncSetAttribute(ff2_kernel,     cudaFuncAttributeMaxDynamicSharedMemorySize, GEMM_SMEM);

  zero_red_kernel<<<1, 32>>>();
  qkv_kernel<<<dim3(128,3), 256, GEMM_SMEM>>>(input1, Wq, Wk, Wv);
  attn_kernel<<<dim3(16,8), 256, ATTN_SMEM>>>(input2, out2, Ws1, bs1, Ws2, bs2);
  outproj_kernel<<<128, 256, GEMM_SMEM>>>(input1, Wo);
  norm_kernel<<<1024, 256>>>(0, nullptr);
  ff1_kernel<<<dim3(128,4), 256, GEMM_SMEM>>>(Wff1);
  ff2_kernel<<<128, 256, GEMM_SMEM>>>(Wff2);
  norm_kernel<<<1024, 256>>>(1, out1);
}

// round 4
// speedup vs baseline: 1.2185x; 1.2185x over previous
#include <cuda_runtime.h>

#define LOG2E 1.4426950408889634f
typedef unsigned long long u64;

// ---------------- f32x2 packed-math helpers (Blackwell dual-FP32) ----------
__device__ __forceinline__ u64 splat2(float x){
  u64 r; asm("mov.b64 %0, {%1,%1};" : "=l"(r) : "f"(x)); return r;
}
__device__ __forceinline__ u64 pack2(float a, float b){
  u64 r; asm("mov.b64 %0, {%1,%2};" : "=l"(r) : "f"(a), "f"(b)); return r;
}
__device__ __forceinline__ void unpack2(u64 v, float& a, float& b){
  asm("mov.b64 {%0,%1}, %2;" : "=f"(a), "=f"(b) : "l"(v));
}
__device__ __forceinline__ u64 ffma2(u64 a, u64 b, u64 c){
  u64 d; asm("fma.rn.f32x2 %0, %1, %2, %3;" : "=l"(d) : "l"(a), "l"(b), "l"(c));
  return d;
}
__device__ __forceinline__ u64 fmul2(u64 a, u64 b){
  u64 d; asm("mul.rn.f32x2 %0, %1, %2;" : "=l"(d) : "l"(a), "l"(b)); return d;
}
__device__ __forceinline__ float fexp2(float x){
  float y; asm("ex2.approx.ftz.f32 %0, %1;" : "=f"(y) : "f"(x)); return y;
}

// ---------------- scratch (device globals; no allocation allowed) ----------
__device__ float g_Q [8192*128];
__device__ float g_K [8192*128];
__device__ float g_V [8192*128];
__device__ float g_O [8192*128];
__device__ float g_Y [8192*128];
__device__ float g_X1[8192*128];
__device__ float g_FF[8192*512];
__device__ float g_red[2][8][2];   // [stage][sample][sum, sumsq]

__global__ void zero_red_kernel(){
  int t = threadIdx.x;
  if (t < 32) ((float*)g_red)[t] = 0.f;
}

// ---------------- shared GEMM microkernel: C[64][128], K-chunk=128 ---------
// Thread map: tr = tid>>5 owns rows tr*8..tr*8+7 ; lane owns cols lane*4..+3.
// f32x2: columns packed in pairs (free from float4 B loads), A splatted on ALU
// pipe. FMA-pipe cost per k4: 64 FFMA2 (was 128 FFMA).
__device__ __forceinline__ void gemm_compute2(const float* As, const float* Ws,
                                              u64 acc[8][2], int r0, int lane){
  #pragma unroll
  for (int k4 = 0; k4 < 32; k4++){
    u64 b[4][2];
    #pragma unroll
    for (int j = 0; j < 4; j++){
      ulonglong2 bv = ((const ulonglong2*)Ws)[(k4*4+j)*32 + lane];
      b[j][0] = bv.x; b[j][1] = bv.y;
    }
    #pragma unroll
    for (int i = 0; i < 8; i++){
      float4 a = ((const float4*)As)[(r0+i)*32 + k4];
      u64 s0 = splat2(a.x), s1 = splat2(a.y), s2 = splat2(a.z), s3 = splat2(a.w);
      acc[i][0] = ffma2(s0, b[0][0], acc[i][0]);
      acc[i][1] = ffma2(s0, b[0][1], acc[i][1]);
      acc[i][0] = ffma2(s1, b[1][0], acc[i][0]);
      acc[i][1] = ffma2(s1, b[1][1], acc[i][1]);
      acc[i][0] = ffma2(s2, b[2][0], acc[i][0]);
      acc[i][1] = ffma2(s2, b[2][1], acc[i][1]);
      acc[i][0] = ffma2(s3, b[3][0], acc[i][0]);
      acc[i][1] = ffma2(s3, b[3][1], acc[i][1]);
    }
  }
}

__device__ __forceinline__ void ln_reduce_store(float s, float sq, float* sm,
                                                int tid, int b, int which){
  #pragma unroll
  for (int off = 16; off; off >>= 1){
    s  += __shfl_xor_sync(0xffffffffu, s,  off);
    sq += __shfl_xor_sync(0xffffffffu, sq, off);
  }
  __syncthreads();
  if ((tid & 31) == 0){ sm[tid>>5] = s; sm[8 + (tid>>5)] = sq; }
  __syncthreads();
  if (tid == 0){
    float S = 0.f, SQ = 0.f;
    #pragma unroll
    for (int w = 0; w < 8; w++){ S += sm[w]; SQ += sm[8+w]; }
    atomicAdd(&g_red[which][b][0], S);
    atomicAdd(&g_red[which][b][1], SQ);
  }
}

// ---------------- K1: QKV projections -------------------------------------
__global__ void __launch_bounds__(256) qkv_kernel(const float* __restrict__ x,
    const float* __restrict__ Wq, const float* __restrict__ Wk,
    const float* __restrict__ Wv){
  extern __shared__ float sm[];
  float* As = sm;             // 64*128
  float* Ws = sm + 64*128;    // 128*128
  int row0 = blockIdx.x * 64;
  const float* W = (blockIdx.y==0) ? Wq : (blockIdx.y==1 ? Wk : Wv);
  float* outp    = (blockIdx.y==0) ? g_Q : (blockIdx.y==1 ? g_K : g_V);
  int tid = threadIdx.x;

  #pragma unroll
  for (int rep = 0; rep < 8; rep++){
    int idx = rep*256 + tid;
    int r = idx >> 5, k4 = idx & 31;
    ((float4*)As)[idx] = ((const float4*)(x + (size_t)(row0+r)*128))[k4];
  }
  #pragma unroll
  for (int rep = 0; rep < 16; rep++){
    int idx = rep*256 + tid;               // Ws[e][j], j = h*32+k
    int e = idx >> 5, j4 = idx & 31;
    ((float4*)Ws)[idx] =
      *(const float4*)(W + ((j4>>3)<<12) + (e<<5) + ((j4&7)<<2));
  }
  __syncthreads();

  int tr = tid >> 5, lane = tid & 31;
  int r0 = tr*8, c0 = lane*4;
  u64 acc[8][2];
  #pragma unroll
  for (int i=0;i<8;i++){ acc[i][0]=splat2(0.f); acc[i][1]=splat2(0.f); }
  gemm_compute2(As, Ws, acc, r0, lane);
  #pragma unroll
  for (int i=0;i<8;i++){
    float c[4];
    unpack2(acc[i][0], c[0], c[1]); unpack2(acc[i][1], c[2], c[3]);
    *(float4*)(outp + (size_t)(row0+r0+i)*128 + c0) =
      make_float4(c[0],c[1],c[2],c[3]);
  }
}

// ---------------- K2: fused attention -------------------------------------
__global__ void __launch_bounds__(256,1) attn_kernel(
    const float* __restrict__ in2, float* __restrict__ out2,
    const float* __restrict__ Ws1, const float* __restrict__ bs1,
    const float* __restrict__ Ws2, const float* __restrict__ bs2){
  extern __shared__ float sm[];
  float* Qs      = sm;             // 64*128  XOR-swizzled (16B granule)
  float* Ks      = Qs + 8192;      // 64*128  XOR-swizzled
  float* Vs      = Ks + 8192;      // 64*128  plain
  float* Smat    = Vs + 8192;      // 4*64*65 scores -> logits -> p
  float* alpha_s = Smat + 4*64*65; // 256
  float* rsum_s  = alpha_s + 256;  // 256
  float* mw      = rsum_s + 256;   // 36: Ws2(32) + bs2(4)

  int tid = threadIdx.x;
  int n0  = blockIdx.x * 64;
  int b   = blockIdx.y;

  if (tid < 32)       mw[tid] = Ws2[tid];
  else if (tid < 36)  mw[tid] = bs2[tid-32];

  // MLP layer-1 weights live in registers for the whole kernel (smem-limited
  // occupancy => registers are free). Pairs packed over the 8 output channels.
  u64 w1[8][4], b1[4];
  #pragma unroll
  for (int i=0;i<8;i++)
    #pragma unroll
    for (int jp=0;jp<4;jp++)
      w1[i][jp] = *(const u64*)(Ws1 + i*8 + 2*jp);
  #pragma unroll
  for (int jp=0;jp<4;jp++) b1[jp] = *(const u64*)(bs1 + 2*jp);

  // load Q tile (swizzled: k4 ^= (r>>3)&7)
  {
    const float* Qg = g_Q + ((size_t)(b*1024 + n0))*128;
    #pragma unroll
    for (int rep = 0; rep < 8; rep++){
      int idx = rep*256 + tid; int r = idx>>5, k4 = idx&31;
      float4 v = ((const float4*)Qg)[r*32 + k4];
      *(float4*)(Qs + r*128 + ((k4 ^ ((r>>3)&7))<<2)) = v;
    }
  }

  int h = tid >> 6, t = tid & 63;
  int s_ni0 = (t&7)*8, s_mi0 = (t>>3)*8;      // score micro-tile
  int p_ni0 = (t>>3)*8, p_k0  = (t&7)*4;      // PV / output micro-tile
  int qsw = t & 7, ksw = t >> 3;

  u64 O2[8][2];
  #pragma unroll
  for (int i=0;i<8;i++){ O2[i][0]=splat2(0.f); O2[i][1]=splat2(0.f); }
  float rmax = -1e30f, rsum = 0.f;

  const float* in2b = in2  + (size_t)b*1048576;
  float*       o2b  = out2 + (size_t)b*1048576;

  for (int it = 0; it < 16; it++){
    int m0 = it*64;
    __syncthreads();
    {
      const float* Kg = g_K + ((size_t)(b*1024 + m0))*128;
      const float* Vg = g_V + ((size_t)(b*1024 + m0))*128;
      #pragma unroll
      for (int rep = 0; rep < 8; rep++){
        int idx = rep*256 + tid; int r = idx>>5, k4 = idx&31;
        float4 kv = ((const float4*)Kg)[r*32 + k4];
        *(float4*)(Ks + r*128 + ((k4 ^ ((r>>3)&7))<<2)) = kv;
        float4 vv = ((const float4*)Vg)[r*32 + k4];
        *(float4*)(Vs + r*128 + (k4<<2)) = vv;
      }
    }
    __syncthreads();

    // ---- scores: S[h][ni][mi] = Q_h . K_h (f32x2, cols packed) ----------
    {
      u64 acc2[8][4];   // [row i][col pair jp]
      #pragma unroll
      for (int i=0;i<8;i++)
        #pragma unroll
        for (int jp=0;jp<4;jp++) acc2[i][jp] = splat2(0.f);
      int kb = h << 5;
      #pragma unroll
      for (int kk = 0; kk < 32; kk++){
        int k = kb + kk, kidx = k >> 2, kl = k & 3;
        float a[8], bb[8];
        #pragma unroll
        for (int i=0;i<8;i++)
          a[i]  = Qs[(s_ni0+i)*128 + ((kidx ^ qsw)<<2) + kl];
        #pragma unroll
        for (int j=0;j<8;j++)
          bb[j] = Ks[(s_mi0+j)*128 + ((kidx ^ ksw)<<2) + kl];
        u64 bp[4];
        #pragma unroll
        for (int jp=0;jp<4;jp++) bp[jp] = pack2(bb[2*jp], bb[2*jp+1]);
        #pragma unroll
        for (int i=0;i<8;i++){
          u64 sa = splat2(a[i]);
          #pragma unroll
          for (int jp=0;jp<4;jp++) acc2[i][jp] = ffma2(sa, bp[jp], acc2[i][jp]);
        }
      }
      #pragma unroll
      for (int i=0;i<8;i++){
        float* Sr = Smat + ((h<<6) + s_ni0 + i)*65 + s_mi0;
        float c[8];
        #pragma unroll
        for (int jp=0;jp<4;jp++) unpack2(acc2[i][jp], c[2*jp], c[2*jp+1]);
        #pragma unroll
        for (int j=0;j<8;j++) Sr[j] = c[j];
      }
    }
    __syncthreads();

    // ---- 8->8(relu)->4 MLP (f32x2), fused input2 read + passthrough -----
    {
      int ni  = tid >> 2;
      int mi0 = (tid & 3) * 4;
      const float* p0 = in2b + ((size_t)(n0+ni)<<10) + m0;
      float*       q0 = o2b  + ((size_t)(n0+ni)<<10) + m0;
      #pragma unroll
      for (int m4 = 0; m4 < 4; m4++){
        int mbase = mi0 + m4*16;
        float4 t2[4];
        #pragma unroll
        for (int hh=0; hh<4; hh++){
          t2[hh] = *(const float4*)(p0 + (size_t)hh*8388608 + mbase);
          *(float4*)(q0 + (size_t)hh*8388608 + mbase) = t2[hh];
        }
        #pragma unroll
        for (int e=0; e<4; e++){
          int mi = mbase + e;
          float x[8];
          #pragma unroll
          for (int hh=0; hh<4; hh++) x[hh] = Smat[((hh<<6)+ni)*65 + mi];
          x[4] = ((float*)&t2[0])[e]; x[5] = ((float*)&t2[1])[e];
          x[6] = ((float*)&t2[2])[e]; x[7] = ((float*)&t2[3])[e];
          u64 z2[4] = { b1[0], b1[1], b1[2], b1[3] };
          #pragma unroll
          for (int i=0;i<8;i++){
            u64 sx = splat2(x[i]);
            #pragma unroll
            for (int jp=0;jp<4;jp++) z2[jp] = ffma2(sx, w1[i][jp], z2[jp]);
          }
          u64 y2[2] = { *(const u64*)(mw+32), *(const u64*)(mw+34) };
          #pragma unroll
          for (int jp=0;jp<4;jp++){
            float zl, zh; unpack2(z2[jp], zl, zh);
            zl = fmaxf(zl, 0.f); zh = fmaxf(zh, 0.f);
            u64 sl = splat2(zl), sh = splat2(zh);
            int j0 = 2*jp, j1 = 2*jp+1;
            y2[0] = ffma2(sl, *(const u64*)(mw + j0*4),     y2[0]);
            y2[1] = ffma2(sl, *(const u64*)(mw + j0*4 + 2), y2[1]);
            y2[0] = ffma2(sh, *(const u64*)(mw + j1*4),     y2[0]);
            y2[1] = ffma2(sh, *(const u64*)(mw + j1*4 + 2), y2[1]);
          }
          float y[4];
          unpack2(y2[0], y[0], y[1]); unpack2(y2[1], y[2], y[3]);
          #pragma unroll
          for (int hh=0;hh<4;hh++) Smat[((hh<<6)+ni)*65 + mi] = y[hh]*LOG2E;
        }
      }
    }
    __syncthreads();

    // ---- online softmax (1 thread per (h,ni) row) -----------------------
    {
      float* Sr = Smat + tid*65;
      float mt = -1e30f;
      #pragma unroll 8
      for (int mi=0; mi<64; mi++) mt = fmaxf(mt, Sr[mi]);
      float mnew = fmaxf(rmax, mt);
      float al = fexp2(rmax - mnew);
      float st = 0.f;
      #pragma unroll 8
      for (int mi=0; mi<64; mi++){
        float p = fexp2(Sr[mi] - mnew);
        Sr[mi] = p; st += p;
      }
      rsum = rsum*al + st;
      rmax = mnew;
      alpha_s[tid] = al;
      rsum_s[tid]  = rsum;
    }
    __syncthreads();

    // ---- rescale + P @ V (f32x2) ----------------------------------------
    {
      #pragma unroll
      for (int i=0;i<8;i++){
        u64 al = splat2(alpha_s[(h<<6) + p_ni0 + i]);
        O2[i][0] = fmul2(O2[i][0], al);
        O2[i][1] = fmul2(O2[i][1], al);
      }
      #pragma unroll 8
      for (int mi=0; mi<64; mi++){
        ulonglong2 vv =
          *(const ulonglong2*)(Vs + mi*128 + (h<<5) + p_k0);
        float p[8];
        #pragma unroll
        for (int i=0;i<8;i++) p[i] = Smat[((h<<6)+p_ni0+i)*65 + mi];
        #pragma unroll
        for (int i=0;i<8;i++){
          u64 sp = splat2(p[i]);
          O2[i][0] = ffma2(sp, vv.x, O2[i][0]);
          O2[i][1] = ffma2(sp, vv.y, O2[i][1]);
        }
      }
    }
  }

  // final normalize + write heads output
  float* Og = g_O + ((size_t)(b*1024 + n0))*128;
  #pragma unroll
  for (int i=0;i<8;i++){
    float inv = 1.f / rsum_s[(h<<6) + p_ni0 + i];
    float c[4];
    unpack2(O2[i][0], c[0], c[1]); unpack2(O2[i][1], c[2], c[3]);
    *(float4*)(Og + (size_t)(p_ni0+i)*128 + (h<<5) + p_k0) =
      make_float4(c[0]*inv, c[1]*inv, c[2]*inv, c[3]*inv);
  }
}

// ---------------- K3: out-projection + residual + LN sums ------------------
__global__ void __launch_bounds__(256) outproj_kernel(
    const float* __restrict__ input1, const float* __restrict__ Wout){
  extern __shared__ float sm[];
  float* As = sm; float* Ws = sm + 64*128;
  int row0 = blockIdx.x * 64; int tid = threadIdx.x;
  #pragma unroll
  for (int rep=0; rep<8; rep++){
    int idx = rep*256 + tid;
    ((float4*)As)[idx] = ((const float4*)(g_O + (size_t)row0*128))[idx];
  }
  #pragma unroll
  for (int rep=0; rep<16; rep++){
    int idx = rep*256 + tid;
    ((float4*)Ws)[idx] = ((const float4*)Wout)[idx];
  }
  __syncthreads();
  int tr = tid>>5, lane = tid&31, r0 = tr*8, c0 = lane*4;
  u64 acc[8][2];
  #pragma unroll
  for (int i=0;i<8;i++){ acc[i][0]=splat2(0.f); acc[i][1]=splat2(0.f); }
  gemm_compute2(As, Ws, acc, r0, lane);
  float s=0.f, sq=0.f;
  #pragma unroll
  for (int i=0;i<8;i++){
    float c[4];
    unpack2(acc[i][0], c[0], c[1]); unpack2(acc[i][1], c[2], c[3]);
    float4 res = *(const float4*)(input1 + (size_t)(row0+r0+i)*128 + c0);
    float4 o = make_float4(c[0]+res.x, c[1]+res.y, c[2]+res.z, c[3]+res.w);
    *(float4*)(g_Y + (size_t)(row0+r0+i)*128 + c0) = o;
    s  += o.x+o.y+o.z+o.w;
    sq += o.x*o.x+o.y*o.y+o.z*o.z+o.w*o.w;
  }
  ln_reduce_store(s, sq, sm, tid, row0>>10, 0);
}

// ---------------- K5: FF1 (relu) ------------------------------------------
__global__ void __launch_bounds__(256) ff1_kernel(const float* __restrict__ Wff1){
  extern __shared__ float sm[];
  float* As = sm; float* Ws = sm + 64*128;
  int row0 = blockIdx.x * 64, ct = blockIdx.y, tid = threadIdx.x;
  #pragma unroll
  for (int rep=0; rep<8; rep++){
    int idx = rep*256 + tid;
    ((float4*)As)[idx] = ((const float4*)(g_X1 + (size_t)row0*128))[idx];
  }
  #pragma unroll
  for (int rep=0; rep<16; rep++){
    int idx = rep*256 + tid;
    int e = idx>>5, c4 = idx&31;
    ((float4*)Ws)[idx] = *(const float4*)(Wff1 + (size_t)e*512 + ct*128 + c4*4);
  }
  __syncthreads();
  int tr = tid>>5, lane = tid&31, r0 = tr*8, c0 = lane*4;
  u64 acc[8][2];
  #pragma unroll
  for (int i=0;i<8;i++){ acc[i][0]=splat2(0.f); acc[i][1]=splat2(0.f); }
  gemm_compute2(As, Ws, acc, r0, lane);
  #pragma unroll
  for (int i=0;i<8;i++){
    float c[4];
    unpack2(acc[i][0], c[0], c[1]); unpack2(acc[i][1], c[2], c[3]);
    float4 o = make_float4(fmaxf(c[0],0.f), fmaxf(c[1],0.f),
                           fmaxf(c[2],0.f), fmaxf(c[3],0.f));
    *(float4*)(g_FF + (size_t)(row0+r0+i)*512 + ct*128 + c0) = o;
  }
}

// ---------------- K6: FF2 + residual + LN sums -----------------------------
__global__ void __launch_bounds__(256) ff2_kernel(const float* __restrict__ Wff2){
  extern __shared__ float sm[];
  float* As = sm; float* Ws = sm + 64*128;
  int row0 = blockIdx.x * 64, tid = threadIdx.x;
  int tr = tid>>5, lane = tid&31, r0 = tr*8, c0 = lane*4;
  u64 acc[8][2];
  #pragma unroll
  for (int i=0;i<8;i++){ acc[i][0]=splat2(0.f); acc[i][1]=splat2(0.f); }
  for (int ch = 0; ch < 4; ch++){
    __syncthreads();
    #pragma unroll
    for (int rep=0; rep<8; rep++){
      int idx = rep*256 + tid; int r = idx>>5, k4 = idx&31;
      ((float4*)As)[idx] =
        *(const float4*)(g_FF + (size_t)(row0+r)*512 + ch*128 + k4*4);
    }
    #pragma unroll
    for (int rep=0; rep<16; rep++){
      int idx = rep*256 + tid;
      ((float4*)Ws)[idx] = ((const float4*)(Wff2 + (size_t)ch*16384))[idx];
    }
    __syncthreads();
    gemm_compute2(As, Ws, acc, r0, lane);
  }
  float s=0.f, sq=0.f;
  #pragma unroll
  for (int i=0;i<8;i++){
    float c[4];
    unpack2(acc[i][0], c[0], c[1]); unpack2(acc[i][1], c[2], c[3]);
    float4 res = *(const float4*)(g_X1 + (size_t)(row0+r0+i)*128 + c0);
    float4 o = make_float4(c[0]+res.x, c[1]+res.y, c[2]+res.z, c[3]+res.w);
    *(float4*)(g_Y + (size_t)(row0+r0+i)*128 + c0) = o;
    s  += o.x+o.y+o.z+o.w;
    sq += o.x*o.x+o.y*o.y+o.z*o.z+o.w*o.w;
  }
  ln_reduce_store(s, sq, sm, tid, row0>>10, 1);
}

// ---------------- K4/K7: global LayerNorm (ddof=1) -------------------------
__global__ void __launch_bounds__(256) norm_kernel(int which, float* extout){
  float* dst = (which == 0) ? g_X1 : extout;
  int id = blockIdx.x*256 + threadIdx.x;
  int b = (id*4) >> 17;
  float s  = g_red[which][b][0];
  float sq = g_red[which][b][1];
  const float M = 131072.f;
  float mean = s / M;
  float var  = (sq - s*s/M) / (M - 1.f);
  float rstd = rsqrtf(var + 1e-5f);
  float4 v = ((const float4*)g_Y)[id];
  v.x = (v.x-mean)*rstd; v.y = (v.y-mean)*rstd;
  v.z = (v.z-mean)*rstd; v.w = (v.w-mean)*rstd;
  ((float4*)dst)[id] = v;
}

// ---------------- launcher --------------------------------------------------
extern "C" void kernel_launch(void* const* d_in, const int* in_sizes, int n_in,
                              void* d_out, int out_size){
  const float* input1 = (const float*)d_in[0];
  const float* input2 = (const float*)d_in[1];
  const float* Wq  = (const float*)d_in[2];
  const float* Wk  = (const float*)d_in[3];
  const float* Wv  = (const float*)d_in[4];
  const float* Wo  = (const float*)d_in[5];
  const float* Ws1 = (const float*)d_in[6];
  const float* bs1 = (const float*)d_in[7];
  const float* Ws2 = (const float*)d_in[8];
  const float* bs2 = (const float*)d_in[9];
  const float* Wff1 = (const float*)d_in[10];
  const float* Wff2 = (const float*)d_in[11];
  float* out1 = (float*)d_out;
  float* out2 = out1 + 8*1024*128;      // input2 passthrough region

  const int GEMM_SMEM = 98304;          // (64*128 + 128*128) * 4
  const int ATTN_SMEM = 167104;         // Qs/Ks/Vs + Smat + alpha/rsum + mw

  cudaFuncSetAttribute(qkv_kernel,     cudaFuncAttributeMaxDynamicSharedMemorySize, GEMM_SMEM);
  cudaFuncSetAttribute(attn_kernel,    cudaFuncAttributeMaxDynamicSharedMemorySize, ATTN_SMEM);
  cudaFuncSetAttribute(outproj_kernel, cudaFuncAttributeMaxDynamicSharedMemorySize, GEMM_SMEM);
  cudaFuncSetAttribute(ff1_kernel,     cudaFuncAttributeMaxDynamicSharedMemorySize, GEMM_SMEM);
  cudaFuncSetAttribute(ff2_kernel,     cudaFuncAttributeMaxDynamicSharedMemorySize, GEMM_SMEM);

  zero_red_kernel<<<1, 32>>>();
  qkv_kernel<<<dim3(128,3), 256, GEMM_SMEM>>>(input1, Wq, Wk, Wv);
  attn_kernel<<<dim3(16,8), 256, ATTN_SMEM>>>(input2, out2, Ws1, bs1, Ws2, bs2);
  outproj_kernel<<<128, 256, GEMM_SMEM>>>(input1, Wo);
  norm_kernel<<<1024, 256>>>(0, nullptr);
  ff1_kernel<<<dim3(128,4), 256, GEMM_SMEM>>>(Wff1);
  ff2_kernel<<<128, 256, GEMM_SMEM>>>(Wff2);
  norm_kernel<<<1024, 256>>>(1, out1);
}